// round 12
// baseline (speedup 1.0000x reference)
#include <cuda_runtime.h>
#include <cuda_fp16.h>
#include <math.h>
#include <stdint.h>

#define N_GRAPHS 4096
#define NODE_SIZE 512
#define GLOBAL_SIZE 256
#define HIDDEN_SIZE 1024
#define INPUT_SIZE 768   // GLOBAL_SIZE + NODE_SIZE

// W transpose tile counts (32x32 tiles)
#define W1_TILES ((INPUT_SIZE / 32) * (HIDDEN_SIZE / 32))   // 24*32 = 768
#define W2_TILES ((HIDDEN_SIZE / 32) * (GLOBAL_SIZE / 32))  // 32*8  = 256

// ---------------- scratch (static device globals; no allocation) ------------
__device__ __half g_a  [N_GRAPHS * INPUT_SIZE];         // GEMM1 A fp16
__device__ __half g_h  [N_GRAPHS * HIDDEN_SIZE];        // GEMM2 A fp16
__device__ __half g_w1t[HIDDEN_SIZE * INPUT_SIZE];      // W1^T fp16 [N,K]
__device__ __half g_w2t[GLOBAL_SIZE * HIDDEN_SIZE];     // W2^T fp16 [N,K]

// ================= helpers ====================================================
__device__ __forceinline__ uint32_t smem_u32(const void* p) {
    uint32_t a;
    asm("{ .reg .u64 t; cvta.to.shared.u64 t, %1; cvt.u32.u64 %0, t; }"
        : "=r"(a) : "l"(p));
    return a;
}
#define SW128(o) ((o) ^ (((o) >> 3) & 0x70))

__device__ __forceinline__ void ldsm_x4(uint32_t* r, uint32_t addr) {
    asm volatile("ldmatrix.sync.aligned.m8n8.x4.shared.b16 {%0,%1,%2,%3}, [%4];"
                 : "=r"(r[0]), "=r"(r[1]), "=r"(r[2]), "=r"(r[3]) : "r"(addr));
}

__device__ __forceinline__ void mma_f16(float* c, const uint32_t* a,
                                        const uint32_t* b) {
    asm volatile(
        "mma.sync.aligned.m16n8k16.row.col.f32.f16.f16.f32 "
        "{%0,%1,%2,%3}, {%4,%5,%6,%7}, {%8,%9}, {%0,%1,%2,%3};"
        : "+f"(c[0]), "+f"(c[1]), "+f"(c[2]), "+f"(c[3])
        : "r"(a[0]), "r"(a[1]), "r"(a[2]), "r"(a[3]), "r"(b[0]), "r"(b[1]));
}

__device__ __forceinline__ void cp16(uint32_t s, const void* g) {
    asm volatile("cp.async.cg.shared.global [%0], [%1], 16;" :: "r"(s), "l"(g));
}
__device__ __forceinline__ void cp_commit() {
    asm volatile("cp.async.commit_group;" ::: "memory");
}
template <int N>
__device__ __forceinline__ void cp_wait() {
    asm volatile("cp.async.wait_group %0;" :: "n"(N) : "memory");
}

// streaming float4 load (evict-first; x is a 1GB single-use stream)
__device__ __forceinline__ float4 ldcs4(const float* p) {
    float4 v;
    asm volatile("ld.global.cs.v4.f32 {%0,%1,%2,%3}, [%4];"
                 : "=f"(v.x), "=f"(v.y), "=f"(v.z), "=f"(v.w) : "l"(p));
    return v;
}

// ---------------- kernel 1: fused prep ----------------------------------------
// blocks [0, N_GRAPHS):               segment-mean + concat -> g_a (fp16)
// blocks [N_GRAPHS, +W1_TILES):       W1 32x32 transpose tile -> g_w1t
// blocks [N_GRAPHS+W1_TILES, +W2..):  W2 32x32 transpose tile -> g_w2t
// The transpose blocks ride in the HBM-bound mean pass for free.
__device__ __forceinline__ void transpose_tile(
    const float* __restrict__ W, __half* __restrict__ Bt,
    int K, int N, int k0, int n0, int tid, float (*t)[33])
{
    int tx = tid % 32, ty = tid / 32;          // 128 threads: ty in 0..3
    #pragma unroll
    for (int i = 0; i < 32; i += 4)
        t[ty + i][tx] = W[(size_t)(k0 + ty + i) * N + n0 + tx];
    __syncthreads();
    #pragma unroll
    for (int i = 0; i < 32; i += 4)
        Bt[(size_t)(n0 + ty + i) * K + k0 + tx] = __float2half_rn(t[tx][ty + i]);
}

__global__ __launch_bounds__(128) void prep_fused(
    const float* __restrict__ x, const int* __restrict__ batch,
    const float* __restrict__ u,
    const float* __restrict__ W1, const float* __restrict__ W2, int n)
{
    __shared__ float t[32][33];
    const int b = blockIdx.x;

    if (b >= N_GRAPHS) {                       // ---- weight transpose path ----
        int idx = b - N_GRAPHS;
        if (idx < W1_TILES) {
            int kx = idx % (INPUT_SIZE / 32), ny = idx / (INPUT_SIZE / 32);
            transpose_tile(W1, g_w1t, INPUT_SIZE, HIDDEN_SIZE,
                           kx * 32, ny * 32, threadIdx.x, t);
        } else {
            idx -= W1_TILES;
            int kx = idx % (HIDDEN_SIZE / 32), ny = idx / (HIDDEN_SIZE / 32);
            transpose_tile(W2, g_w2t, HIDDEN_SIZE, GLOBAL_SIZE,
                           kx * 32, ny * 32, threadIdx.x, t);
        }
        return;
    }

    // ---- segment mean path ----
    const int g = b;
    int l = 0, r = n;
    while (l < r) { int m = (l + r) >> 1; if (__ldg(&batch[m]) < g) l = m + 1; else r = m; }
    const int lo = l;
    r = n;
    while (l < r) { int m = (l + r) >> 1; if (__ldg(&batch[m]) < g + 1) l = m + 1; else r = m; }
    const int hi = l;

    const int c = threadIdx.x * 4;             // 128 threads x 4 = 512 cols
    float4 acc = make_float4(0.f, 0.f, 0.f, 0.f);

    int rr = lo;
    for (; rr + 8 <= hi; rr += 8) {            // 8-row unroll -> MLP=8
        float4 v0 = ldcs4(x + (size_t)(rr + 0) * NODE_SIZE + c);
        float4 v1 = ldcs4(x + (size_t)(rr + 1) * NODE_SIZE + c);
        float4 v2 = ldcs4(x + (size_t)(rr + 2) * NODE_SIZE + c);
        float4 v3 = ldcs4(x + (size_t)(rr + 3) * NODE_SIZE + c);
        float4 v4 = ldcs4(x + (size_t)(rr + 4) * NODE_SIZE + c);
        float4 v5 = ldcs4(x + (size_t)(rr + 5) * NODE_SIZE + c);
        float4 v6 = ldcs4(x + (size_t)(rr + 6) * NODE_SIZE + c);
        float4 v7 = ldcs4(x + (size_t)(rr + 7) * NODE_SIZE + c);
        acc.x += ((v0.x + v1.x) + (v2.x + v3.x)) + ((v4.x + v5.x) + (v6.x + v7.x));
        acc.y += ((v0.y + v1.y) + (v2.y + v3.y)) + ((v4.y + v5.y) + (v6.y + v7.y));
        acc.z += ((v0.z + v1.z) + (v2.z + v3.z)) + ((v4.z + v5.z) + (v6.z + v7.z));
        acc.w += ((v0.w + v1.w) + (v2.w + v3.w)) + ((v4.w + v5.w) + (v6.w + v7.w));
    }
    for (; rr < hi; ++rr) {
        float4 v = ldcs4(x + (size_t)rr * NODE_SIZE + c);
        acc.x += v.x; acc.y += v.y; acc.z += v.z; acc.w += v.w;
    }

    const float inv = 1.f / fmaxf((float)(hi - lo), 1.f);
    const size_t rowo = (size_t)g * INPUT_SIZE;

    {
        size_t o = rowo + GLOBAL_SIZE + c;
        *reinterpret_cast<__half2*>(&g_a[o]) =
            __halves2half2(__float2half_rn(acc.x * inv), __float2half_rn(acc.y * inv));
        *reinterpret_cast<__half2*>(&g_a[o + 2]) =
            __halves2half2(__float2half_rn(acc.z * inv), __float2half_rn(acc.w * inv));
    }
    if (threadIdx.x < 64) {
        float4 v = *(const float4*)(u + (size_t)g * GLOBAL_SIZE + c);
        size_t o = rowo + c;
        *reinterpret_cast<__half2*>(&g_a[o]) =
            __halves2half2(__float2half_rn(v.x), __float2half_rn(v.y));
        *reinterpret_cast<__half2*>(&g_a[o + 2]) =
            __halves2half2(__float2half_rn(v.z), __float2half_rn(v.w));
    }
}

// ---------------- SELU --------------------------------------------------------
__device__ __forceinline__ float selu_f(float v) {
    const float scale = 1.0507009873554805f;
    const float alpha = 1.6732632423543772f;
    return v > 0.f ? scale * v : scale * alpha * (expf(v) - 1.f);
}

// ================= mma.sync fp16 GEMM, cp.async double-buffered ===============
// C[M,N] = act(A @ Bt^T + bias). A=[M,K] fp16, Bt=[N,K] fp16, fp32 accum.
// 64x64 tiles, ~60 regs -> MINCTA=4 (32 warps/SM) hides ldsm->mma latency.
template <int BM, int BN, int KTOT, int WM, int WN, int MINCTA,
          bool ACT, bool F16OUT>
__global__ void __launch_bounds__(256, MINCTA) mma_gemm(
    const __half* __restrict__ Ah, const __half* __restrict__ Bh,
    const float* __restrict__ bias,
    float* __restrict__ Cf, __half* __restrict__ Ch, int Ntot)
{
    constexpr int KC  = 64;          // K elements per smem stage
    constexpr int RB  = 128;         // bytes per smem row (KC * 2)
    constexpr int WGM = BM / WM;     // warps along M
    constexpr int MT  = WM / 16;
    constexpr int NT  = WN / 8;
    constexpr int STAGE = (BM + BN) * RB;
    static_assert((BM / WM) * (BN / WN) == 8, "8 warps");
    static_assert(NT % 2 == 0, "B ldmatrix.x4 covers 2 n-tiles");

    extern __shared__ char dsm[];
    uint32_t raw = smem_u32(dsm);
    uint32_t sb  = (raw + 1023u) & ~1023u;
    char* base   = dsm + (sb - raw);

    float* biass = (float*)base;     // [BN] floats in first 1024B
    uint32_t AHIa[2], BHIa[2];
    #pragma unroll
    for (int s = 0; s < 2; ++s) {
        uint32_t b0 = sb + 1024 + s * STAGE;
        AHIa[s] = b0;
        BHIa[s] = b0 + BM * RB;
    }

    const int tid  = threadIdx.x;
    const int wid  = tid >> 5;
    const int lane = tid & 31;
    const int bm0  = blockIdx.y * BM;
    const int bn0  = blockIdx.x * BN;
    const int wm0  = (wid % WGM) * WM;
    const int wn0  = (wid / WGM) * WN;

    for (int i = tid; i < BN; i += 256) biass[i] = bias[bn0 + i];

    float acc[MT][NT][4];
    #pragma unroll
    for (int i = 0; i < MT; ++i)
        #pragma unroll
        for (int j = 0; j < NT; ++j)
            #pragma unroll
            for (int q = 0; q < 4; ++q) acc[i][j][q] = 0.f;

    constexpr int A_IT = BM * 8 / 256;
    constexpr int B_IT = BN * 8 / 256;

    auto load_stage = [&](int kcc, int s) {
        const int kel = kcc * KC;
        #pragma unroll
        for (int i = 0; i < A_IT; ++i) {
            int e = tid + i * 256;
            int row = e >> 3, seg = e & 7;
            uint32_t so = SW128((uint32_t)(row * RB + seg * 16));
            size_t ga = (size_t)(bm0 + row) * KTOT + kel + seg * 8;
            cp16(AHIa[s] + so, Ah + ga);
        }
        #pragma unroll
        for (int i = 0; i < B_IT; ++i) {
            int e = tid + i * 256;
            int row = e >> 3, seg = e & 7;
            uint32_t so = SW128((uint32_t)(row * RB + seg * 16));
            size_t gb = (size_t)(bn0 + row) * KTOT + kel + seg * 8;
            cp16(BHIa[s] + so, Bh + gb);
        }
        cp_commit();
    };

    const int g  = lane >> 3;
    const int lr = lane & 7;
    const uint32_t a_row_off = (uint32_t)(wm0 + (g & 1) * 8 + lr) * RB + (uint32_t)(g >> 1) * 16;
    const uint32_t b_row_off = (uint32_t)(wn0 + (g >> 1) * 8 + lr) * RB + (uint32_t)(g & 1) * 16;

    constexpr int NCH = KTOT / KC;
    load_stage(0, 0);

    for (int kc = 0; kc < NCH; ++kc) {
        const int buf = kc & 1;
        if (kc + 1 < NCH) {
            load_stage(kc + 1, buf ^ 1);
            cp_wait<1>();
        } else {
            cp_wait<0>();
        }
        __syncthreads();

        const uint32_t AHIb = AHIa[buf], BHIb = BHIa[buf];

        #pragma unroll
        for (int ks = 0; ks < 4; ++ks) {
            const uint32_t kb = (uint32_t)ks * 32;

            uint32_t a_hi[MT][4];
            #pragma unroll
            for (int mt = 0; mt < MT; ++mt)
                ldsm_x4(a_hi[mt], AHIb + SW128(a_row_off + (uint32_t)mt * 16 * RB + kb));
            uint32_t b_hi[NT][2];
            #pragma unroll
            for (int np = 0; np < NT / 2; ++np) {
                uint32_t th[4];
                ldsm_x4(th, BHIb + SW128(b_row_off + (uint32_t)np * 16 * RB + kb));
                b_hi[np * 2][0] = th[0]; b_hi[np * 2][1] = th[1];
                b_hi[np * 2 + 1][0] = th[2]; b_hi[np * 2 + 1][1] = th[3];
            }
            #pragma unroll
            for (int mt = 0; mt < MT; ++mt)
                #pragma unroll
                for (int nt = 0; nt < NT; ++nt)
                    mma_f16(acc[mt][nt], a_hi[mt], b_hi[nt]);
        }
        __syncthreads();
    }

    // ---- epilogue: bias + act, write out ----
    const int er = lane >> 2;
    const int ec = (lane & 3) * 2;
    #pragma unroll
    for (int mt = 0; mt < MT; ++mt) {
        #pragma unroll
        for (int nt = 0; nt < NT; ++nt) {
            int col = wn0 + nt * 8 + ec;
            float bx = biass[col], by = biass[col + 1];
            float v0 = acc[mt][nt][0] + bx, v1 = acc[mt][nt][1] + by;
            float v2 = acc[mt][nt][2] + bx, v3 = acc[mt][nt][3] + by;
            if (ACT) { v0 = selu_f(v0); v1 = selu_f(v1); v2 = selu_f(v2); v3 = selu_f(v3); }
            size_t r0 = (size_t)(bm0 + wm0 + mt * 16 + er);
            size_t r1 = r0 + 8;
            size_t o0 = r0 * Ntot + bn0 + col;
            size_t o1 = r1 * Ntot + bn0 + col;
            if (F16OUT) {
                *reinterpret_cast<__half2*>(&Ch[o0]) =
                    __halves2half2(__float2half_rn(v0), __float2half_rn(v1));
                *reinterpret_cast<__half2*>(&Ch[o1]) =
                    __halves2half2(__float2half_rn(v2), __float2half_rn(v3));
            } else {
                *reinterpret_cast<float2*>(&Cf[o0]) = make_float2(v0, v1);
                *reinterpret_cast<float2*>(&Cf[o1]) = make_float2(v2, v3);
            }
        }
    }
}

// ---------------- launch ------------------------------------------------------
extern "C" void kernel_launch(void* const* d_in, const int* in_sizes, int n_in,
                              void* d_out, int out_size)
{
    const float* x     = (const float*)d_in[0];
    // d_in[1] = edge_index (unused), d_in[2] = edge_attr (unused)
    const float* u     = (const float*)d_in[3];
    const int*   batch = (const int*)d_in[4];
    const float* W1    = (const float*)d_in[5];
    const float* b1    = (const float*)d_in[6];
    const float* W2    = (const float*)d_in[7];
    const float* b2    = (const float*)d_in[8];
    float*       out   = (float*)d_out;

    const int n_nodes = in_sizes[0] / NODE_SIZE;

    void *p_a, *p_h, *p_w1, *p_w2;
    cudaGetSymbolAddress(&p_a,  g_a);
    cudaGetSymbolAddress(&p_h,  g_h);
    cudaGetSymbolAddress(&p_w1, g_w1t);
    cudaGetSymbolAddress(&p_w2, g_w2t);

    // 64x64 tiles: smem = 1024 + 2*(64+64)*128 = 33792 -> 4 CTAs/SM (reg-capped)
    constexpr int SMB = 1024 + 2 * (64 + 64) * 128;
    cudaFuncSetAttribute(
        (const void*)mma_gemm<64, 64, INPUT_SIZE, 16, 32, 4, true, true>,
        cudaFuncAttributeMaxDynamicSharedMemorySize, SMB);
    cudaFuncSetAttribute(
        (const void*)mma_gemm<64, 64, HIDDEN_SIZE, 16, 32, 4, false, false>,
        cudaFuncAttributeMaxDynamicSharedMemorySize, SMB);

    // fused: segment-mean (HBM-bound) + weight transposes riding for free
    prep_fused<<<N_GRAPHS + W1_TILES + W2_TILES, 128>>>(
        x, batch, u, W1, W2, n_nodes);

    // GEMM1: [4096,768] @ [768,1024] + b1, SELU -> g_h (fp16)
    mma_gemm<64, 64, INPUT_SIZE, 16, 32, 4, true, true>
        <<<dim3(HIDDEN_SIZE / 64, N_GRAPHS / 64), 256, SMB>>>(
            (const __half*)p_a, (const __half*)p_w1,
            b1, nullptr, (__half*)p_h, HIDDEN_SIZE);

    // GEMM2: [4096,1024] @ [1024,256] + b2 -> out (fp32)
    mma_gemm<64, 64, HIDDEN_SIZE, 16, 32, 4, false, false>
        <<<dim3(GLOBAL_SIZE / 64, N_GRAPHS / 64), 256, SMB>>>(
            (const __half*)p_h, (const __half*)p_w2,
            b2, out, nullptr, GLOBAL_SIZE);
}